// round 9
// baseline (speedup 1.0000x reference)
#include <cuda_runtime.h>
#include <cuda_fp16.h>
#include <math.h>
#include <stdint.h>

#define S_TOT 2304
#define S0    2048
#define DIM   1536
#define NH    24
#define HD    64
#define QKV_N 4608
#define XK    3072          // split-fp16 K layout: [hi 0:1536 | lo 1536:3072]

// GEMM staging: CTA tile 256(M) x 128(N), K-chunk 64, 2-stage
#define N_STAGE 24
#define KCH     64
#define APITCH  144                 // bytes per smem row (128B data + 16B pad)
#define AH_OFF  0
#define AL_OFF  36864               // 256*144
#define BH_OFF  73728
#define BL_OFF  92160               // +128*144
#define STAGE_B 110592
#define GEMM_SMEM (2 * STAGE_B)     // 221184

// Attention staging
#define BQ 128
#define BK 64
#define AP_B 272                    // bytes per K/V smem row (128 halves + 8 pad)
#define KV_TILE_B (64 * AP_B)       // 17408
#define STAGE2_B (2 * KV_TILE_B)    // K + V per stage = 34816
#define ATT_SMEM (2 * STAGE2_B)     // 69632 double-buffered
#define N_KT (S_TOT / BK)           // 36

// ---------------- scratch (device globals; no allocation allowed) -----------
__device__ float  g_q[NH * S_TOT * HD];       // fp32 q (pre-norm)
__device__ float  g_k[NH * S_TOT * HD];       // fp32 k (pre-norm)
__device__ __half g_qs[NH * S_TOT * 128];     // q split fp16 [hi 64 | lo 64], pre-scaled
__device__ __half g_ks[NH * S_TOT * 128];     // k split fp16
__device__ __half g_vs[NH * S_TOT * 128];     // v split fp16
__device__ __half g_xh [S_TOT * XK];          // x (split fp16), K-major
__device__ __half g_ah [S_TOT * XK];          // attention out (split fp16)
__device__ __half g_wq0[QKV_N * XK];          // w_qkv0^T (split fp16), [N][K']
__device__ __half g_wq1[QKV_N * XK];
__device__ __half g_wo0[DIM * XK];            // w_out0^T
__device__ __half g_wo1[DIM * XK];

// ---------------- helpers ----------------------------------------------------
__device__ __forceinline__ uint32_t smem_u32(const void* p) {
    uint32_t a;
    asm("{ .reg .u64 t; cvta.to.shared.u64 t, %1; cvt.u32.u64 %0, t; }"
        : "=r"(a) : "l"(p));
    return a;
}
__device__ __forceinline__ void cp16(uint32_t dst, const void* src) {
    asm volatile("cp.async.cg.shared.global [%0], [%1], 16;"
                 :: "r"(dst), "l"(src));
}
__device__ __forceinline__ void ldsm_x4(uint32_t* r, uint32_t addr) {
    asm volatile("ldmatrix.sync.aligned.m8n8.x4.shared.b16 {%0,%1,%2,%3}, [%4];"
                 : "=r"(r[0]), "=r"(r[1]), "=r"(r[2]), "=r"(r[3]) : "r"(addr));
}
__device__ __forceinline__ void ldsm_x4_t(uint32_t* r, uint32_t addr) {
    asm volatile("ldmatrix.sync.aligned.m8n8.x4.trans.shared.b16 {%0,%1,%2,%3}, [%4];"
                 : "=r"(r[0]), "=r"(r[1]), "=r"(r[2]), "=r"(r[3]) : "r"(addr));
}
__device__ __forceinline__ void mma16816(float* c, const uint32_t* a,
                                         const uint32_t* b) {
    asm volatile(
        "mma.sync.aligned.m16n8k16.row.col.f32.f16.f16.f32 "
        "{%0,%1,%2,%3}, {%4,%5,%6,%7}, {%8,%9}, {%0,%1,%2,%3};"
        : "+f"(c[0]), "+f"(c[1]), "+f"(c[2]), "+f"(c[3])
        : "r"(a[0]), "r"(a[1]), "r"(a[2]), "r"(a[3]), "r"(b[0]), "r"(b[1]));
}

// ---------------- conversion: x -> split fp16 -------------------------------
__global__ __launch_bounds__(256) void convert_x_kernel(
    const float* __restrict__ x0, const float* __restrict__ x1)
{
    int idx = blockIdx.x * 256 + threadIdx.x;
    if (idx >= S_TOT * DIM) return;
    int s = idx / DIM, k = idx - s * DIM;
    float v = (s < S0) ? x0[(size_t)s * DIM + k] : x1[(size_t)(s - S0) * DIM + k];
    __half hi = __float2half_rn(v);
    __half lo = __float2half_rn(v - __half2float(hi));
    g_xh[(size_t)s * XK + k] = hi;
    g_xh[(size_t)s * XK + DIM + k] = lo;
}

// ---------------- conversion: weights -> transposed split fp16 --------------
__global__ __launch_bounds__(256) void convert_w_kernel(
    const float* __restrict__ src, int N, int sel)
{
    __shared__ float tile[32][33];
    __half* dst = (sel == 0) ? g_wq0 : (sel == 1) ? g_wq1 : (sel == 2) ? g_wo0 : g_wo1;
    int n0 = blockIdx.x * 32;
    int k0 = blockIdx.y * 32;
    int tx = threadIdx.x, ty = threadIdx.y;   // (32, 8)
#pragma unroll
    for (int i = 0; i < 32; i += 8)
        tile[ty + i][tx] = src[(size_t)(k0 + ty + i) * N + n0 + tx];
    __syncthreads();
#pragma unroll
    for (int i = 0; i < 32; i += 8) {
        int n = n0 + ty + i;
        int k = k0 + tx;
        float v = tile[tx][ty + i];
        __half hi = __float2half_rn(v);
        __half lo = __float2half_rn(v - __half2float(hi));
        dst[(size_t)n * XK + k] = hi;
        dst[(size_t)n * XK + DIM + k] = lo;
    }
}

// ---------------- mma.sync split-fp16 GEMM, 256x128 tile, 64x64 warp tile ---
// MODE 0: A=g_xh, B=wq by modality; q,k -> fp32 g_q/g_k, v -> split-fp16 g_vs.
// MODE 1: A=g_ah, B=wo by modality; write d_out.
template <int MODE>
__global__ __launch_bounds__(256, 1) void gemm_mma(float* __restrict__ out)
{
    extern __shared__ char sm[];
    const int tid = threadIdx.x;
    const int wid = tid >> 5;
    const int lane = tid & 31;
    const int m0 = blockIdx.y * 256;
    const int n0 = blockIdx.x * 128;

    const __half* A = (MODE == 0) ? g_xh : g_ah;
    const __half* B;
    if (MODE == 0) B = (m0 < S0) ? g_wq0 : g_wq1;
    else           B = (m0 < S0) ? g_wo0 : g_wo1;

    const uint32_t smb = smem_u32(sm);

    // loaders: A one thread per row (8 cp16/tile); B two threads per row (4 each)
    const __half* gA = A + (size_t)(m0 + tid) * XK;
    const uint32_t sAoff = (uint32_t)tid * APITCH;
    const int tBr = tid >> 1;
    const int tBc = tid & 1;
    const __half* gB = B + (size_t)(n0 + tBr) * XK + tBc * 32;
    const uint32_t sBoff = (uint32_t)tBr * APITCH + tBc * 64;

    // warp layout: 4(M) x 2(N), warp tile 64x64
    const int wm = wid >> 1;
    const int wn = wid & 1;
    const uint32_t lm_a = (uint32_t)(wm * 64 + (lane & 15)) * APITCH + (lane >> 4) * 16;
    const uint32_t lm_b = (uint32_t)(wn * 64 + (lane & 15)) * APITCH + (lane >> 4) * 16;

    float acc[4][8][4];
#pragma unroll
    for (int i = 0; i < 4; i++)
#pragma unroll
        for (int j = 0; j < 8; j++)
#pragma unroll
            for (int e = 0; e < 4; e++) acc[i][j][e] = 0.0f;

    // ---- prologue: stage 0 ----
    {
        uint32_t d = smb;
#pragma unroll
        for (int i = 0; i < 8; i++) {
            cp16(d + AH_OFF + sAoff + i * 16, gA + i * 8);
            cp16(d + AL_OFF + sAoff + i * 16, gA + DIM + i * 8);
        }
#pragma unroll
        for (int i = 0; i < 4; i++) {
            cp16(d + BH_OFF + sBoff + i * 16, gB + i * 8);
            cp16(d + BL_OFF + sBoff + i * 16, gB + DIM + i * 8);
        }
        asm volatile("cp.async.commit_group;" ::: "memory");
    }

#pragma unroll 1
    for (int s = 0; s < N_STAGE; s++) {
        if (s + 1 < N_STAGE) {
            uint32_t d = smb + ((s + 1) & 1) * STAGE_B;
            const __half* pa = gA + (s + 1) * KCH;
            const __half* pb = gB + (s + 1) * KCH;
#pragma unroll
            for (int i = 0; i < 8; i++) {
                cp16(d + AH_OFF + sAoff + i * 16, pa + i * 8);
                cp16(d + AL_OFF + sAoff + i * 16, pa + DIM + i * 8);
            }
#pragma unroll
            for (int i = 0; i < 4; i++) {
                cp16(d + BH_OFF + sBoff + i * 16, pb + i * 8);
                cp16(d + BL_OFF + sBoff + i * 16, pb + DIM + i * 8);
            }
            asm volatile("cp.async.commit_group;" ::: "memory");
            asm volatile("cp.async.wait_group 1;" ::: "memory");
        } else {
            asm volatile("cp.async.wait_group 0;" ::: "memory");
        }
        __syncthreads();

        const uint32_t sb = smb + (s & 1) * STAGE_B;
#pragma unroll
        for (int ks = 0; ks < 4; ks++) {
            const uint32_t aa = sb + lm_a + ks * 32;
            const uint32_t ba = sb + BH_OFF + lm_b + ks * 32;
            uint32_t ah[4][4], al[4][4], bh[8][2], bl[8][2];
#pragma unroll
            for (int mt = 0; mt < 4; mt++) {
                ldsm_x4(ah[mt], aa + mt * 16 * APITCH);
                ldsm_x4(al[mt], aa + AL_OFF + mt * 16 * APITCH);
            }
#pragma unroll
            for (int np = 0; np < 4; np++) {
                uint32_t r[4];
                ldsm_x4(r, ba + np * 16 * APITCH);
                bh[2 * np][0] = r[0]; bh[2 * np][1] = r[2];
                bh[2 * np + 1][0] = r[1]; bh[2 * np + 1][1] = r[3];
                ldsm_x4(r, ba + (BL_OFF - BH_OFF) + np * 16 * APITCH);
                bl[2 * np][0] = r[0]; bl[2 * np][1] = r[2];
                bl[2 * np + 1][0] = r[1]; bl[2 * np + 1][1] = r[3];
            }
#pragma unroll
            for (int mt = 0; mt < 4; mt++)
#pragma unroll
                for (int nt = 0; nt < 8; nt++) {
                    mma16816(acc[mt][nt], ah[mt], bh[nt]);
                    mma16816(acc[mt][nt], ah[mt], bl[nt]);
                    mma16816(acc[mt][nt], al[mt], bh[nt]);
                }
        }
        __syncthreads();   // protect buffer (s&1) from next iteration's cp.async
    }

    // ---- epilogue ----
    const int g  = lane >> 2;
    const int tg = lane & 3;
#pragma unroll
    for (int mt = 0; mt < 4; mt++) {
        const int m = m0 + wm * 64 + mt * 16 + g;
#pragma unroll
        for (int nt = 0; nt < 8; nt++) {
            const int col = n0 + wn * 64 + nt * 8 + tg * 2;
            if (MODE == 0) {
                int tsel = col / DIM;
                int rem = col - tsel * DIM;
                int h = rem >> 6;
                int d = rem & 63;
                if (tsel < 2) {
                    float* dstb = (tsel == 0 ? g_q : g_k);
                    float* p0 = dstb + ((size_t)h * S_TOT + m) * HD + d;
                    *(float2*)p0            = make_float2(acc[mt][nt][0], acc[mt][nt][1]);
                    *(float2*)(p0 + 8 * HD) = make_float2(acc[mt][nt][2], acc[mt][nt][3]);
                } else {
                    // v -> split fp16 [hi 0:64 | lo 64:128]
                    __half* vb = g_vs + ((size_t)h * S_TOT + m) * 128 + d;
#pragma unroll
                    for (int rr = 0; rr < 2; rr++) {
                        float a0 = acc[mt][nt][rr * 2 + 0];
                        float a1 = acc[mt][nt][rr * 2 + 1];
                        __half2 hp = __floats2half2_rn(a0, a1);
                        float2 hf = __half22float2(hp);
                        __half2 lp = __floats2half2_rn(a0 - hf.x, a1 - hf.y);
                        __half* p = vb + (size_t)rr * 8 * 128;
                        *(__half2*)p        = hp;
                        *(__half2*)(p + 64) = lp;
                    }
                }
            } else {
                float* p0 = out + (size_t)m * DIM + col;
                *(float2*)p0             = make_float2(acc[mt][nt][0], acc[mt][nt][1]);
                *(float2*)(p0 + 8 * DIM) = make_float2(acc[mt][nt][2], acc[mt][nt][3]);
            }
        }
    }
}

// ---------------- RMSNorm + RoPE -> split fp16 q (pre-scaled) / k -----------
__global__ __launch_bounds__(256) void norm_rope_kernel(
    const float* __restrict__ gq0, const float* __restrict__ gk0,
    const float* __restrict__ gq1, const float* __restrict__ gk1)
{
    const int warp = (blockIdx.x * blockDim.x + threadIdx.x) >> 5;
    const int lane = threadIdx.x & 31;
    if (warp >= NH * S_TOT) return;
    const int h = warp / S_TOT;
    const int s = warp - h * S_TOT;

    const float* gq;
    const float* gk;
    int pos;
    if (s < S0) { gq = gq0; gk = gk0; pos = s; }
    else        { gq = gq1; gk = gk1; pos = s - S0; }

    const double LN1E4_OVER_32 = 0.2878231217852968;  // ln(10000)/32
    float inv = (float)exp(-(double)lane * LN1E4_OVER_32);
    float f = (float)pos * inv;
    float cs, sn;
    sincosf(f, &sn, &cs);

    const size_t base   = ((size_t)h * S_TOT + s) * HD;
    const size_t base2  = ((size_t)h * S_TOT + s) * 128;
    const float gql = gq[lane], gqh = gq[lane + 32];
    const float gkl = gk[lane], gkh = gk[lane + 32];

    {
        float lo = g_q[base + lane];
        float hi = g_q[base + lane + 32];
        float ss = lo * lo + hi * hi;
#pragma unroll
        for (int off = 16; off; off >>= 1)
            ss += __shfl_xor_sync(0xffffffffu, ss, off);
        float r = rsqrtf(ss * (1.0f / 64.0f) + 1e-6f);
        float nl = lo * r * gql;
        float nh = hi * r * gqh;
        float q0 = (nl * cs - nh * sn) * 0.125f;   // fold 1/sqrt(D)
        float q1 = (nh * cs + nl * sn) * 0.125f;
        __half h0 = __float2half_rn(q0), h1 = __float2half_rn(q1);
        g_qs[base2 + lane]       = h0;
        g_qs[base2 + lane + 32]  = h1;
        g_qs[base2 + 64 + lane]      = __float2half_rn(q0 - __half2float(h0));
        g_qs[base2 + 96 + lane]      = __float2half_rn(q1 - __half2float(h1));
    }
    {
        float lo = g_k[base + lane];
        float hi = g_k[base + lane + 32];
        float ss = lo * lo + hi * hi;
#pragma unroll
        for (int off = 16; off; off >>= 1)
            ss += __shfl_xor_sync(0xffffffffu, ss, off);
        float r = rsqrtf(ss * (1.0f / 64.0f) + 1e-6f);
        float nl = lo * r * gkl;
        float nh = hi * r * gkh;
        float k0 = nl * cs - nh * sn;
        float k1 = nh * cs + nl * sn;
        __half h0 = __float2half_rn(k0), h1 = __float2half_rn(k1);
        g_ks[base2 + lane]       = h0;
        g_ks[base2 + lane + 32]  = h1;
        g_ks[base2 + 64 + lane]      = __float2half_rn(k0 - __half2float(h0));
        g_ks[base2 + 96 + lane]      = __float2half_rn(k1 - __half2float(h1));
    }
}

// ---------------- flash attention on mma.sync, split fp16 -------------------
// CTA: 128 queries x 1 head, 8 warps (16 q-rows each). K-tiles of 64 keys.
__global__ __launch_bounds__(256, 1) void attn_mma_kernel()
{
    extern __shared__ char sm[];
    const uint32_t smb = smem_u32(sm);
    const int tid = threadIdx.x;
    const int wq = tid >> 5;
    const int lane = tid & 31;
    const int h = blockIdx.y;
    const int q0 = blockIdx.x * BQ;

    const __half* Qg = g_qs + ((size_t)h * S_TOT + q0) * 128;
    const __half* Kg = g_ks + (size_t)h * S_TOT * 128;
    const __half* Vg = g_vs + (size_t)h * S_TOT * 128;

    // ---- Q tile -> smem (stage-0 area) -> register fragments ----
    {
        int rid = tid >> 1;
        int hb = (tid & 1) * 128;
        const char* src = (const char*)(Qg + (size_t)rid * 128) + hb;
        uint32_t dst = smb + (uint32_t)rid * AP_B + hb;
#pragma unroll
        for (int i = 0; i < 8; i++) cp16(dst + i * 16, src + i * 16);
        asm volatile("cp.async.commit_group;" ::: "memory");
        asm volatile("cp.async.wait_group 0;" ::: "memory");
    }
    __syncthreads();

    uint32_t qh[4][4], ql[4][4];
    {
        uint32_t base = smb + (uint32_t)(wq * 16 + (lane & 15)) * AP_B
                      + (lane >> 4) * 16;
#pragma unroll
        for (int c = 0; c < 4; c++) {
            ldsm_x4(qh[c], base + c * 32);
            ldsm_x4(ql[c], base + 128 + c * 32);
        }
    }
    __syncthreads();

    // cp.async coords for K/V tiles: 4 threads per 256B row
    const int rid4 = tid >> 2;
    const int slot = (tid & 3) * 64;

    // ldmatrix per-lane offsets
    const int grp = lane >> 3, lr = lane & 7;
    const uint32_t k_off = (uint32_t)((grp >> 1) * 8 + lr) * AP_B + (grp & 1) * 16;
    const uint32_t v_off = (uint32_t)((grp & 1) * 8 + lr) * AP_B + (grp >> 1) * 16;

    float o[8][4];
#pragma unroll
    for (int j = 0; j < 8; j++)
#pragma unroll
        for (int e = 0; e < 4; e++) o[j][e] = 0.0f;
    float m0 = -1e30f, m8 = -1e30f, l0 = 0.0f, l8 = 0.0f;

    // prefetch tile 0 into stage 0
    {
        const char* ks = (const char*)(Kg + (size_t)rid4 * 128) + slot;
        const char* vs = (const char*)(Vg + (size_t)rid4 * 128) + slot;
        uint32_t kd = smb + (uint32_t)rid4 * AP_B + slot;
#pragma unroll
        for (int i = 0; i < 4; i++) {
            cp16(kd + i * 16,             ks + i * 16);
            cp16(kd + KV_TILE_B + i * 16, vs + i * 16);
        }
        asm volatile("cp.async.commit_group;" ::: "memory");
    }

#pragma unroll 1
    for (int it = 0; it < N_KT; it++) {
        if (it + 1 < N_KT) {
            const size_t krow = (size_t)((it + 1) * BK + rid4) * 128;
            const char* ks = (const char*)(Kg + krow) + slot;
            const char* vs = (const char*)(Vg + krow) + slot;
            uint32_t kd = smb + ((it + 1) & 1) * STAGE2_B + (uint32_t)rid4 * AP_B + slot;
#pragma unroll
            for (int i = 0; i < 4; i++) {
                cp16(kd + i * 16,             ks + i * 16);
                cp16(kd + KV_TILE_B + i * 16, vs + i * 16);
            }
            asm volatile("cp.async.commit_group;" ::: "memory");
            asm volatile("cp.async.wait_group 1;" ::: "memory");
        } else {
            asm volatile("cp.async.wait_group 0;" ::: "memory");
        }
        __syncthreads();

        const uint32_t kb = smb + (it & 1) * STAGE2_B;
        const uint32_t vb = kb + KV_TILE_B;

        // ---- scores: S = Q K^T (3 split passes), fp32 accum ----
        float sc[8][4];
#pragma unroll
        for (int j = 0; j < 8; j++)
#pragma unroll
            for (int e = 0; e < 4; e++) sc[j][e] = 0.0f;

#pragma unroll
        for (int c = 0; c < 4; c++) {
            uint32_t kf[8][2], kl[8][2];
#pragma unroll
            for (int jp = 0; jp < 4; jp++) {
                uint32_t r[4];
                uint32_t a = kb + k_off + (uint32_t)jp * 16 * AP_B + c * 32;
                ldsm_x4(r, a);
                kf[2 * jp][0] = r[0]; kf[2 * jp][1] = r[1];
                kf[2 * jp + 1][0] = r[2]; kf[2 * jp + 1][1] = r[3];
                ldsm_x4(r, a + 128);
                kl[2 * jp][0] = r[0]; kl[2 * jp][1] = r[1];
                kl[2 * jp + 1][0] = r[2]; kl[2 * jp + 1][1] = r[3];
            }
#pragma unroll
            for (int j = 0; j < 8; j++) {
                mma16816(sc[j], qh[c], kf[j]);
                mma16816(sc[j], qh[c], kl[j]);
                mma16816(sc[j], ql[c], kf[j]);
            }
        }

        // ---- online softmax on fragments ----
        float mx0 = sc[0][0], mx8 = sc[0][2];
#pragma unroll
        for (int j = 0; j < 8; j++) {
            mx0 = fmaxf(mx0, fmaxf(sc[j][0], sc[j][1]));
            mx8 = fmaxf(mx8, fmaxf(sc[j][2], sc[j][3]));
        }
        mx0 = fmaxf(mx0, __shfl_xor_sync(0xffffffffu, mx0, 1));
        mx0 = fmaxf(mx0, __shfl_xor_sync(0xffffffffu, mx0, 2));
        mx8 = fmaxf(mx8, __shfl_xor_sync(0xffffffffu, mx8, 1));
        mx8 = fmaxf(mx8, __shfl_xor_sync(0xffffffffu, mx8, 2));
        float mn0 = fmaxf(m0, mx0), mn8 = fmaxf(m8, mx8);
        float cr0 = __expf(m0 - mn0), cr8 = __expf(m8 - mn8);
        m0 = mn0; m8 = mn8;
        l0 *= cr0; l8 *= cr8;

        uint32_t pha[8], phb[8], pla[8], plb[8];
#pragma unroll
        for (int j = 0; j < 8; j++) {
            float p0 = __expf(sc[j][0] - m0);
            float p1 = __expf(sc[j][1] - m0);
            float p2 = __expf(sc[j][2] - m8);
            float p3 = __expf(sc[j][3] - m8);
            l0 += p0 + p1; l8 += p2 + p3;
            __half2 ha = __floats2half2_rn(p0, p1);
            float2 fa = __half22float2(ha);
            __half2 la = __floats2half2_rn(p0 - fa.x, p1 - fa.y);
            __half2 hb = __floats2half2_rn(p2, p3);
            float2 fb = __half22float2(hb);
            __half2 lb = __floats2half2_rn(p2 - fb.x, p3 - fb.y);
            pha[j] = *(uint32_t*)&ha; pla[j] = *(uint32_t*)&la;
            phb[j] = *(uint32_t*)&hb; plb[j] = *(uint32_t*)&lb;
        }
#pragma unroll
        for (int j = 0; j < 8; j++) {
            o[j][0] *= cr0; o[j][1] *= cr0;
            o[j][2] *= cr8; o[j][3] *= cr8;
        }

        // ---- O += P V (3 split passes) ----
#pragma unroll
        for (int c = 0; c < 4; c++) {
            uint32_t a_h[4] = {pha[2 * c], phb[2 * c], pha[2 * c + 1], phb[2 * c + 1]};
            uint32_t a_l[4] = {pla[2 * c], plb[2 * c], pla[2 * c + 1], plb[2 * c + 1]};
            uint32_t vh[8][2], vl[8][2];
#pragma unroll
            for (int jp = 0; jp < 4; jp++) {
                uint32_t r[4];
                uint32_t a = vb + v_off + (uint32_t)c * 16 * AP_B + jp * 32;
                ldsm_x4_t(r, a);
                vh[2 * jp][0] = r[0]; vh[2 * jp][1] = r[1];
                vh[2 * jp + 1][0] = r[2]; vh[2 * jp + 1][1] = r[3];
                ldsm_x4_t(r, a + 128);
                vl[2 * jp][0] = r[0]; vl[2 * jp][1] = r[1];
                vl[2 * jp + 1][0] = r[2]; vl[2 * jp + 1][1] = r[3];
            }
#pragma unroll
            for (int j = 0; j < 8; j++) {
                mma16816(o[j], a_h, vh[j]);
                mma16816(o[j], a_h, vl[j]);
                mma16816(o[j], a_l, vh[j]);
            }
        }
        __syncthreads();
    }

    // ---- finalize: divide by l, write split fp16 into g_ah ----
    l0 += __shfl_xor_sync(0xffffffffu, l0, 1);
    l0 += __shfl_xor_sync(0xffffffffu, l0, 2);
    l8 += __shfl_xor_sync(0xffffffffu, l8, 1);
    l8 += __shfl_xor_sync(0xffffffffu, l8, 2);
    const float iv0 = 1.0f / l0, iv8 = 1.0f / l8;

    const int g = lane >> 2, tg = lane & 3;
    const int r0 = q0 + wq * 16 + g;
    __half* out0 = g_ah + (size_t)r0 * XK + h * HD + tg * 2;
    __half* out8 = out0 + (size_t)8 * XK;
#pragma unroll
    for (int j = 0; j < 8; j++) {
        float a0 = o[j][0] * iv0, a1 = o[j][1] * iv0;
        __half2 hp = __floats2half2_rn(a0, a1);
        float2 hf = __half22float2(hp);
        __half2 lp = __floats2half2_rn(a0 - hf.x, a1 - hf.y);
        *(__half2*)(out0 + 8 * j)       = hp;
        *(__half2*)(out0 + 8 * j + DIM) = lp;
        float b0 = o[j][2] * iv8, b1 = o[j][3] * iv8;
        hp = __floats2half2_rn(b0, b1);
        hf = __half22float2(hp);
        lp = __floats2half2_rn(b0 - hf.x, b1 - hf.y);
        *(__half2*)(out8 + 8 * j)       = hp;
        *(__half2*)(out8 + 8 * j + DIM) = lp;
    }
}

// ---------------- launch ----------------------------------------------------
extern "C" void kernel_launch(void* const* d_in, const int* in_sizes, int n_in,
                              void* d_out, int out_size)
{
    const float* x0     = (const float*)d_in[0];
    const float* x1     = (const float*)d_in[1];
    const float* w_qkv0 = (const float*)d_in[2];
    const float* w_qkv1 = (const float*)d_in[3];
    const float* w_out0 = (const float*)d_in[4];
    const float* w_out1 = (const float*)d_in[5];
    const float* gq0    = (const float*)d_in[6];
    const float* gk0    = (const float*)d_in[7];
    const float* gq1    = (const float*)d_in[8];
    const float* gk1    = (const float*)d_in[9];
    float* out = (float*)d_out;

    cudaFuncSetAttribute(gemm_mma<0>, cudaFuncAttributeMaxDynamicSharedMemorySize, GEMM_SMEM);
    cudaFuncSetAttribute(gemm_mma<1>, cudaFuncAttributeMaxDynamicSharedMemorySize, GEMM_SMEM);
    cudaFuncSetAttribute(attn_mma_kernel, cudaFuncAttributeMaxDynamicSharedMemorySize, ATT_SMEM);

    // 0: fp32 -> split fp16 conversions
    convert_x_kernel<<<(S_TOT * DIM + 255) / 256, 256>>>(x0, x1);
    convert_w_kernel<<<dim3(QKV_N / 32, DIM / 32), dim3(32, 8)>>>(w_qkv0, QKV_N, 0);
    convert_w_kernel<<<dim3(QKV_N / 32, DIM / 32), dim3(32, 8)>>>(w_qkv1, QKV_N, 1);
    convert_w_kernel<<<dim3(DIM / 32,   DIM / 32), dim3(32, 8)>>>(w_out0, DIM, 2);
    convert_w_kernel<<<dim3(DIM / 32,   DIM / 32), dim3(32, 8)>>>(w_out1, DIM, 3);

    // A: QKV projection (tensor cores) -> q,k fp32; v split fp16
    gemm_mma<0><<<dim3(QKV_N / 128, S_TOT / 256), 256, GEMM_SMEM>>>(nullptr);

    // B: RMSNorm + RoPE -> split fp16 q (pre-scaled), k
    {
        int warps = NH * S_TOT;
        norm_rope_kernel<<<(warps * 32 + 255) / 256, 256>>>(gq0, gk0, gq1, gk1);
    }

    // C: flash attention on tensor cores -> split fp16 g_ah
    attn_mma_kernel<<<dim3(S_TOT / BQ, NH), 256, ATT_SMEM>>>();

    // D: output projection (tensor cores)
    gemm_mma<1><<<dim3(DIM / 128, S_TOT / 256), 256, GEMM_SMEM>>>(out);
}

// round 10
// speedup vs baseline: 1.5245x; 1.5245x over previous
#include <cuda_runtime.h>
#include <cuda_fp16.h>
#include <math.h>
#include <stdint.h>

#define S_TOT 2304
#define S0    2048
#define DIM   1536
#define NH    24
#define HD    64
#define QKV_N 4608
#define XK    3072          // split-fp16 K layout: [hi 0:1536 | lo 1536:3072]

// GEMM staging: CTA 128x128, K-chunk 64, tiles {Ah, Bh, Bl}, 2-stage
#define N_STAGE 24
#define KCH     64
#define PITCH   72                  // halves per smem row (pad 8)
#define TILE_B  (128 * PITCH * 2)   // 18432 B per operand tile
#define STAGE_B (3 * TILE_B)        // Ah, Bh, Bl = 55296
#define GEMM_SMEM (2 * STAGE_B)     // 110592 double-buffered

// Attention staging
#define BQ 128
#define BK 64
#define AP_B 272                    // bytes per K/V smem row (128 halves + 8 pad)
#define KV_TILE_B (64 * AP_B)       // 17408
#define STAGE2_B (2 * KV_TILE_B)    // K + V per stage = 34816
#define ATT_SMEM (2 * STAGE2_B)     // 69632 double-buffered
#define N_KT (S_TOT / BK)           // 36

// ---------------- scratch (device globals; no allocation allowed) -----------
__device__ float  g_q[NH * S_TOT * HD];       // fp32 q (pre-norm)
__device__ float  g_k[NH * S_TOT * HD];       // fp32 k (pre-norm)
__device__ __half g_qs[NH * S_TOT * 128];     // q fp16 hi (pre-scaled); lo unused
__device__ __half g_ks[NH * S_TOT * 128];     // k split fp16 [hi 64 | lo 64]
__device__ __half g_vs[NH * S_TOT * 128];     // v split fp16
__device__ __half g_xh [S_TOT * XK];          // x fp16 hi (lo plane unused)
__device__ __half g_ah [S_TOT * XK];          // attention out fp16 hi (lo unused)
__device__ __half g_wq0[QKV_N * XK];          // w_qkv0^T (split fp16), [N][K']
__device__ __half g_wq1[QKV_N * XK];
__device__ __half g_wo0[DIM * XK];            // w_out0^T
__device__ __half g_wo1[DIM * XK];

// ---------------- helpers ----------------------------------------------------
__device__ __forceinline__ uint32_t smem_u32(const void* p) {
    uint32_t a;
    asm("{ .reg .u64 t; cvta.to.shared.u64 t, %1; cvt.u32.u64 %0, t; }"
        : "=r"(a) : "l"(p));
    return a;
}
__device__ __forceinline__ void cp16(uint32_t dst, const void* src) {
    asm volatile("cp.async.cg.shared.global [%0], [%1], 16;"
                 :: "r"(dst), "l"(src));
}
__device__ __forceinline__ void ldsm_x4(uint32_t* r, uint32_t addr) {
    asm volatile("ldmatrix.sync.aligned.m8n8.x4.shared.b16 {%0,%1,%2,%3}, [%4];"
                 : "=r"(r[0]), "=r"(r[1]), "=r"(r[2]), "=r"(r[3]) : "r"(addr));
}
__device__ __forceinline__ void ldsm_x4_t(uint32_t* r, uint32_t addr) {
    asm volatile("ldmatrix.sync.aligned.m8n8.x4.trans.shared.b16 {%0,%1,%2,%3}, [%4];"
                 : "=r"(r[0]), "=r"(r[1]), "=r"(r[2]), "=r"(r[3]) : "r"(addr));
}
__device__ __forceinline__ void ldsm_x2(uint32_t* r, uint32_t addr) {
    asm volatile("ldmatrix.sync.aligned.m8n8.x2.shared.b16 {%0,%1}, [%2];"
                 : "=r"(r[0]), "=r"(r[1]) : "r"(addr));
}
__device__ __forceinline__ void mma16816(float* c, const uint32_t* a,
                                         const uint32_t* b) {
    asm volatile(
        "mma.sync.aligned.m16n8k16.row.col.f32.f16.f16.f32 "
        "{%0,%1,%2,%3}, {%4,%5,%6,%7}, {%8,%9}, {%0,%1,%2,%3};"
        : "+f"(c[0]), "+f"(c[1]), "+f"(c[2]), "+f"(c[3])
        : "r"(a[0]), "r"(a[1]), "r"(a[2]), "r"(a[3]), "r"(b[0]), "r"(b[1]));
}

// ---------------- conversion: x -> fp16 hi -----------------------------------
__global__ __launch_bounds__(256) void convert_x_kernel(
    const float* __restrict__ x0, const float* __restrict__ x1)
{
    int idx = blockIdx.x * 256 + threadIdx.x;
    if (idx >= S_TOT * DIM) return;
    int s = idx / DIM, k = idx - s * DIM;
    float v = (s < S0) ? x0[(size_t)s * DIM + k] : x1[(size_t)(s - S0) * DIM + k];
    g_xh[(size_t)s * XK + k] = __float2half_rn(v);
}

// ---------------- conversion: weights -> transposed split fp16 --------------
__global__ __launch_bounds__(256) void convert_w_kernel(
    const float* __restrict__ src, int N, int sel)
{
    __shared__ float tile[32][33];
    __half* dst = (sel == 0) ? g_wq0 : (sel == 1) ? g_wq1 : (sel == 2) ? g_wo0 : g_wo1;
    int n0 = blockIdx.x * 32;
    int k0 = blockIdx.y * 32;
    int tx = threadIdx.x, ty = threadIdx.y;   // (32, 8)
#pragma unroll
    for (int i = 0; i < 32; i += 8)
        tile[ty + i][tx] = src[(size_t)(k0 + ty + i) * N + n0 + tx];
    __syncthreads();
#pragma unroll
    for (int i = 0; i < 32; i += 8) {
        int n = n0 + ty + i;
        int k = k0 + tx;
        float v = tile[tx][ty + i];
        __half hi = __float2half_rn(v);
        __half lo = __float2half_rn(v - __half2float(hi));
        dst[(size_t)n * XK + k] = hi;
        dst[(size_t)n * XK + DIM + k] = lo;
    }
}

// ---------------- mma.sync 2-pass GEMM, 128x128 tile ------------------------
// acc = Ah*(Bh+Bl); residual Al*B dropped (~1.5e-4 rel).
// MODE 0: A=g_xh, B=wq by modality; q,k -> fp32 g_q/g_k, v -> split-fp16 g_vs.
// MODE 1: A=g_ah, B=wo by modality; write d_out.
template <int MODE>
__global__ __launch_bounds__(256, 1) void gemm_mma(float* __restrict__ out)
{
    extern __shared__ char sm[];
    const int tid = threadIdx.x;
    const int wid = tid >> 5;
    const int lane = tid & 31;
    const int m0 = blockIdx.y * 128;
    const int n0 = blockIdx.x * 128;

    const __half* A = (MODE == 0) ? g_xh : g_ah;
    const __half* B;
    if (MODE == 0) B = (m0 < S0) ? g_wq0 : g_wq1;
    else           B = (m0 < S0) ? g_wo0 : g_wo1;

    const uint32_t smb = smem_u32(sm);

    // global->smem: 2 threads per row, 4x16B each per tile
    const int lrow  = tid >> 1;
    const int lslot = (tid & 1) * 4;
    const __half* gA = A + (size_t)(m0 + lrow) * XK + lslot * 8;
    const __half* gB = B + (size_t)(n0 + lrow) * XK + lslot * 8;
    const uint32_t sOff = (uint32_t)lrow * (PITCH * 2) + lslot * 16;

    const int wm = wid >> 2;
    const int wn = wid & 3;

    const int arow = wm * 64 + (lane & 15);
    const uint32_t aoffs = (uint32_t)arow * (PITCH * 2) + (lane >> 4) * 16;
    const int brow = wn * 32 + (lane & 7);
    const uint32_t boffs = (uint32_t)brow * (PITCH * 2) + ((lane >> 3) & 1) * 16;

    float acc[4][4][4];
#pragma unroll
    for (int i = 0; i < 4; i++)
#pragma unroll
        for (int j = 0; j < 4; j++)
#pragma unroll
            for (int e = 0; e < 4; e++) acc[i][j][e] = 0.0f;

    {
        uint32_t d = smb + sOff;
#pragma unroll
        for (int i = 0; i < 4; i++) {
            cp16(d + i * 16,              gA + i * 8);
            cp16(d + TILE_B + i * 16,     gB + i * 8);
            cp16(d + 2 * TILE_B + i * 16, gB + DIM + i * 8);
        }
        asm volatile("cp.async.commit_group;" ::: "memory");
    }

#pragma unroll 1
    for (int s = 0; s < N_STAGE; s++) {
        if (s + 1 < N_STAGE) {
            uint32_t d = smb + ((s + 1) & 1) * STAGE_B + sOff;
            const __half* pa = gA + (s + 1) * KCH;
            const __half* pb = gB + (s + 1) * KCH;
#pragma unroll
            for (int i = 0; i < 4; i++) {
                cp16(d + i * 16,              pa + i * 8);
                cp16(d + TILE_B + i * 16,     pb + i * 8);
                cp16(d + 2 * TILE_B + i * 16, pb + DIM + i * 8);
            }
            asm volatile("cp.async.commit_group;" ::: "memory");
            asm volatile("cp.async.wait_group 1;" ::: "memory");
        } else {
            asm volatile("cp.async.wait_group 0;" ::: "memory");
        }
        __syncthreads();

        const uint32_t sb = smb + (s & 1) * STAGE_B;
#pragma unroll
        for (int ks = 0; ks < 4; ks++) {
            const uint32_t aA = sb + aoffs + ks * 32;
            const uint32_t aB = sb + TILE_B + boffs + ks * 32;
            uint32_t ah[4][4], bh[4][2], bl[4][2];
#pragma unroll
            for (int mt = 0; mt < 4; mt++)
                ldsm_x4(ah[mt], aA + mt * 16 * (PITCH * 2));
#pragma unroll
            for (int nt = 0; nt < 4; nt++) {
                ldsm_x2(bh[nt], aB + nt * 8 * (PITCH * 2));
                ldsm_x2(bl[nt], aB + TILE_B + nt * 8 * (PITCH * 2));
            }
#pragma unroll
            for (int mt = 0; mt < 4; mt++)
#pragma unroll
                for (int nt = 0; nt < 4; nt++) {
                    mma16816(acc[mt][nt], ah[mt], bh[nt]);
                    mma16816(acc[mt][nt], ah[mt], bl[nt]);
                }
        }
        __syncthreads();   // protect buffer (s&1) from next iteration's cp.async
    }

    // ---- epilogue ----
    const int g  = lane >> 2;
    const int tg = lane & 3;
#pragma unroll
    for (int mt = 0; mt < 4; mt++) {
        const int m = m0 + wm * 64 + mt * 16 + g;
#pragma unroll
        for (int nt = 0; nt < 4; nt++) {
            const int col = n0 + wn * 32 + nt * 8 + tg * 2;
            if (MODE == 0) {
                int tsel = col / DIM;
                int rem = col - tsel * DIM;
                int h = rem >> 6;
                int d = rem & 63;
                if (tsel < 2) {
                    float* dstb = (tsel == 0 ? g_q : g_k);
                    float* p0 = dstb + ((size_t)h * S_TOT + m) * HD + d;
                    *(float2*)p0            = make_float2(acc[mt][nt][0], acc[mt][nt][1]);
                    *(float2*)(p0 + 8 * HD) = make_float2(acc[mt][nt][2], acc[mt][nt][3]);
                } else {
                    // v -> split fp16 [hi 0:64 | lo 64:128]
                    __half* vb = g_vs + ((size_t)h * S_TOT + m) * 128 + d;
#pragma unroll
                    for (int rr = 0; rr < 2; rr++) {
                        float a0 = acc[mt][nt][rr * 2 + 0];
                        float a1 = acc[mt][nt][rr * 2 + 1];
                        __half2 hp = __floats2half2_rn(a0, a1);
                        float2 hf = __half22float2(hp);
                        __half2 lp = __floats2half2_rn(a0 - hf.x, a1 - hf.y);
                        __half* p = vb + (size_t)rr * 8 * 128;
                        *(__half2*)p        = hp;
                        *(__half2*)(p + 64) = lp;
                    }
                }
            } else {
                float* p0 = out + (size_t)m * DIM + col;
                *(float2*)p0             = make_float2(acc[mt][nt][0], acc[mt][nt][1]);
                *(float2*)(p0 + 8 * DIM) = make_float2(acc[mt][nt][2], acc[mt][nt][3]);
            }
        }
    }
}

// ---------------- RMSNorm + RoPE -> fp16 q hi (pre-scaled) / k split --------
__global__ __launch_bounds__(256) void norm_rope_kernel(
    const float* __restrict__ gq0, const float* __restrict__ gk0,
    const float* __restrict__ gq1, const float* __restrict__ gk1)
{
    const int warp = (blockIdx.x * blockDim.x + threadIdx.x) >> 5;
    const int lane = threadIdx.x & 31;
    if (warp >= NH * S_TOT) return;
    const int h = warp / S_TOT;
    const int s = warp - h * S_TOT;

    const float* gq;
    const float* gk;
    int pos;
    if (s < S0) { gq = gq0; gk = gk0; pos = s; }
    else        { gq = gq1; gk = gk1; pos = s - S0; }

    const double LN1E4_OVER_32 = 0.2878231217852968;  // ln(10000)/32
    float inv = (float)exp(-(double)lane * LN1E4_OVER_32);
    float f = (float)pos * inv;
    float cs, sn;
    sincosf(f, &sn, &cs);

    const size_t base   = ((size_t)h * S_TOT + s) * HD;
    const size_t base2  = ((size_t)h * S_TOT + s) * 128;
    const float gql = gq[lane], gqh = gq[lane + 32];
    const float gkl = gk[lane], gkh = gk[lane + 32];

    {
        float lo = g_q[base + lane];
        float hi = g_q[base + lane + 32];
        float ss = lo * lo + hi * hi;
#pragma unroll
        for (int off = 16; off; off >>= 1)
            ss += __shfl_xor_sync(0xffffffffu, ss, off);
        float r = rsqrtf(ss * (1.0f / 64.0f) + 1e-6f);
        float nl = lo * r * gql;
        float nh = hi * r * gqh;
        float q0 = (nl * cs - nh * sn) * 0.125f;   // fold 1/sqrt(D)
        float q1 = (nh * cs + nl * sn) * 0.125f;
        g_qs[base2 + lane]      = __float2half_rn(q0);
        g_qs[base2 + lane + 32] = __float2half_rn(q1);
    }
    {
        float lo = g_k[base + lane];
        float hi = g_k[base + lane + 32];
        float ss = lo * lo + hi * hi;
#pragma unroll
        for (int off = 16; off; off >>= 1)
            ss += __shfl_xor_sync(0xffffffffu, ss, off);
        float r = rsqrtf(ss * (1.0f / 64.0f) + 1e-6f);
        float nl = lo * r * gkl;
        float nh = hi * r * gkh;
        float k0 = nl * cs - nh * sn;
        float k1 = nh * cs + nl * sn;
        __half h0 = __float2half_rn(k0), h1 = __float2half_rn(k1);
        g_ks[base2 + lane]       = h0;
        g_ks[base2 + lane + 32]  = h1;
        g_ks[base2 + 64 + lane]  = __float2half_rn(k0 - __half2float(h0));
        g_ks[base2 + 96 + lane]  = __float2half_rn(k1 - __half2float(h1));
    }
}

// ---------------- flash attention on mma.sync, 2-pass split -----------------
// CTA: 128 queries x 1 head, 8 warps (16 q-rows each). K-tiles of 64 keys.
__global__ __launch_bounds__(256, 1) void attn_mma_kernel()
{
    extern __shared__ char sm[];
    const uint32_t smb = smem_u32(sm);
    const int tid = threadIdx.x;
    const int wq = tid >> 5;
    const int lane = tid & 31;
    const int h = blockIdx.y;
    const int q0 = blockIdx.x * BQ;

    const __half* Qg = g_qs + ((size_t)h * S_TOT + q0) * 128;
    const __half* Kg = g_ks + (size_t)h * S_TOT * 128;
    const __half* Vg = g_vs + (size_t)h * S_TOT * 128;

    // ---- Q tile (hi plane only) -> smem -> register fragments ----
    {
        int rid = tid >> 1;
        int hb = (tid & 1) * 64;
        const char* src = (const char*)(Qg + (size_t)rid * 128) + hb;
        uint32_t dst = smb + (uint32_t)rid * AP_B + hb;
#pragma unroll
        for (int i = 0; i < 4; i++) cp16(dst + i * 16, src + i * 16);
        asm volatile("cp.async.commit_group;" ::: "memory");
        asm volatile("cp.async.wait_group 0;" ::: "memory");
    }
    __syncthreads();

    uint32_t qh[4][4];
    {
        uint32_t base = smb + (uint32_t)(wq * 16 + (lane & 15)) * AP_B
                      + (lane >> 4) * 16;
#pragma unroll
        for (int c = 0; c < 4; c++)
            ldsm_x4(qh[c], base + c * 32);
    }
    __syncthreads();

    // cp.async coords for K/V tiles: 4 threads per 256B row
    const int rid4 = tid >> 2;
    const int slot = (tid & 3) * 64;

    // ldmatrix per-lane offsets
    const int grp = lane >> 3, lr = lane & 7;
    const uint32_t k_off = (uint32_t)((grp >> 1) * 8 + lr) * AP_B + (grp & 1) * 16;
    const uint32_t v_off = (uint32_t)((grp & 1) * 8 + lr) * AP_B + (grp >> 1) * 16;

    float o[8][4];
#pragma unroll
    for (int j = 0; j < 8; j++)
#pragma unroll
        for (int e = 0; e < 4; e++) o[j][e] = 0.0f;
    float m0 = -1e30f, m8 = -1e30f, l0 = 0.0f, l8 = 0.0f;

    // prefetch tile 0 into stage 0
    {
        const char* ks = (const char*)(Kg + (size_t)rid4 * 128) + slot;
        const char* vs = (const char*)(Vg + (size_t)rid4 * 128) + slot;
        uint32_t kd = smb + (uint32_t)rid4 * AP_B + slot;
#pragma unroll
        for (int i = 0; i < 4; i++) {
            cp16(kd + i * 16,             ks + i * 16);
            cp16(kd + KV_TILE_B + i * 16, vs + i * 16);
        }
        asm volatile("cp.async.commit_group;" ::: "memory");
    }

#pragma unroll 1
    for (int it = 0; it < N_KT; it++) {
        if (it + 1 < N_KT) {
            const size_t krow = (size_t)((it + 1) * BK + rid4) * 128;
            const char* ks = (const char*)(Kg + krow) + slot;
            const char* vs = (const char*)(Vg + krow) + slot;
            uint32_t kd = smb + ((it + 1) & 1) * STAGE2_B + (uint32_t)rid4 * AP_B + slot;
#pragma unroll
            for (int i = 0; i < 4; i++) {
                cp16(kd + i * 16,             ks + i * 16);
                cp16(kd + KV_TILE_B + i * 16, vs + i * 16);
            }
            asm volatile("cp.async.commit_group;" ::: "memory");
            asm volatile("cp.async.wait_group 1;" ::: "memory");
        } else {
            asm volatile("cp.async.wait_group 0;" ::: "memory");
        }
        __syncthreads();

        const uint32_t kb = smb + (it & 1) * STAGE2_B;
        const uint32_t vb = kb + KV_TILE_B;

        // ---- scores: S = qh * (Kh + Kl), fp32 accum (2 passes) ----
        float sc[8][4];
#pragma unroll
        for (int j = 0; j < 8; j++)
#pragma unroll
            for (int e = 0; e < 4; e++) sc[j][e] = 0.0f;

#pragma unroll
        for (int c = 0; c < 4; c++) {
            uint32_t kf[8][2], kl[8][2];
#pragma unroll
            for (int jp = 0; jp < 4; jp++) {
                uint32_t r[4];
                uint32_t a = kb + k_off + (uint32_t)jp * 16 * AP_B + c * 32;
                ldsm_x4(r, a);
                kf[2 * jp][0] = r[0]; kf[2 * jp][1] = r[1];
                kf[2 * jp + 1][0] = r[2]; kf[2 * jp + 1][1] = r[3];
                ldsm_x4(r, a + 128);
                kl[2 * jp][0] = r[0]; kl[2 * jp][1] = r[1];
                kl[2 * jp + 1][0] = r[2]; kl[2 * jp + 1][1] = r[3];
            }
#pragma unroll
            for (int j = 0; j < 8; j++) {
                mma16816(sc[j], qh[c], kf[j]);
                mma16816(sc[j], qh[c], kl[j]);
            }
        }

        // ---- online softmax on fragments ----
        float mx0 = sc[0][0], mx8 = sc[0][2];
#pragma unroll
        for (int j = 0; j < 8; j++) {
            mx0 = fmaxf(mx0, fmaxf(sc[j][0], sc[j][1]));
            mx8 = fmaxf(mx8, fmaxf(sc[j][2], sc[j][3]));
        }
        mx0 = fmaxf(mx0, __shfl_xor_sync(0xffffffffu, mx0, 1));
        mx0 = fmaxf(mx0, __shfl_xor_sync(0xffffffffu, mx0, 2));
        mx8 = fmaxf(mx8, __shfl_xor_sync(0xffffffffu, mx8, 1));
        mx8 = fmaxf(mx8, __shfl_xor_sync(0xffffffffu, mx8, 2));
        float mn0 = fmaxf(m0, mx0), mn8 = fmaxf(m8, mx8);
        float cr0 = __expf(m0 - mn0), cr8 = __expf(m8 - mn8);
        m0 = mn0; m8 = mn8;
        l0 *= cr0; l8 *= cr8;

        uint32_t pha[8], phb[8];
#pragma unroll
        for (int j = 0; j < 8; j++) {
            float p0 = __expf(sc[j][0] - m0);
            float p1 = __expf(sc[j][1] - m0);
            float p2 = __expf(sc[j][2] - m8);
            float p3 = __expf(sc[j][3] - m8);
            l0 += p0 + p1; l8 += p2 + p3;
            __half2 ha = __floats2half2_rn(p0, p1);
            __half2 hb = __floats2half2_rn(p2, p3);
            pha[j] = *(uint32_t*)&ha;
            phb[j] = *(uint32_t*)&hb;
        }
#pragma unroll
        for (int j = 0; j < 8; j++) {
            o[j][0] *= cr0; o[j][1] *= cr0;
            o[j][2] *= cr8; o[j][3] *= cr8;
        }

        // ---- O += Ph * (Vh + Vl) (2 passes) ----
#pragma unroll
        for (int c = 0; c < 4; c++) {
            uint32_t a_h[4] = {pha[2 * c], phb[2 * c], pha[2 * c + 1], phb[2 * c + 1]};
            uint32_t vh[8][2], vl[8][2];
#pragma unroll
            for (int jp = 0; jp < 4; jp++) {
                uint32_t r[4];
                uint32_t a = vb + v_off + (uint32_t)c * 16 * AP_B + jp * 32;
                ldsm_x4_t(r, a);
                vh[2 * jp][0] = r[0]; vh[2 * jp][1] = r[1];
                vh[2 * jp + 1][0] = r[2]; vh[2 * jp + 1][1] = r[3];
                ldsm_x4_t(r, a + 128);
                vl[2 * jp][0] = r[0]; vl[2 * jp][1] = r[1];
                vl[2 * jp + 1][0] = r[2]; vl[2 * jp + 1][1] = r[3];
            }
#pragma unroll
            for (int j = 0; j < 8; j++) {
                mma16816(o[j], a_h, vh[j]);
                mma16816(o[j], a_h, vl[j]);
            }
        }
        __syncthreads();
    }

    // ---- finalize: divide by l, write fp16 hi into g_ah ----
    l0 += __shfl_xor_sync(0xffffffffu, l0, 1);
    l0 += __shfl_xor_sync(0xffffffffu, l0, 2);
    l8 += __shfl_xor_sync(0xffffffffu, l8, 1);
    l8 += __shfl_xor_sync(0xffffffffu, l8, 2);
    const float iv0 = 1.0f / l0, iv8 = 1.0f / l8;

    const int g = lane >> 2, tg = lane & 3;
    const int r0 = q0 + wq * 16 + g;
    __half* out0 = g_ah + (size_t)r0 * XK + h * HD + tg * 2;
    __half* out8 = out0 + (size_t)8 * XK;
#pragma unroll
    for (int j = 0; j < 8; j++) {
        *(__half2*)(out0 + 8 * j) = __floats2half2_rn(o[j][0] * iv0, o[j][1] * iv0);
        *(__half2*)(out8 + 8 * j) = __floats2half2_rn(o[j][2] * iv8, o[j][3] * iv8);
    }
}

// ---------------- launch ----------------------------------------------------
extern "C" void kernel_launch(void* const* d_in, const int* in_sizes, int n_in,
                              void* d_out, int out_size)
{
    const float* x0     = (const float*)d_in[0];
    const float* x1     = (const float*)d_in[1];
    const float* w_qkv0 = (const float*)d_in[2];
    const float* w_qkv1 = (const float*)d_in[3];
    const float* w_out0 = (const float*)d_in[4];
    const float* w_out1 = (const float*)d_in[5];
    const float* gq0    = (const float*)d_in[6];
    const float* gk0    = (const float*)d_in[7];
    const float* gq1    = (const float*)d_in[8];
    const float* gk1    = (const float*)d_in[9];
    float* out = (float*)d_out;

    cudaFuncSetAttribute(gemm_mma<0>, cudaFuncAttributeMaxDynamicSharedMemorySize, GEMM_SMEM);
    cudaFuncSetAttribute(gemm_mma<1>, cudaFuncAttributeMaxDynamicSharedMemorySize, GEMM_SMEM);
    cudaFuncSetAttribute(attn_mma_kernel, cudaFuncAttributeMaxDynamicSharedMemorySize, ATT_SMEM);

    // 0: fp32 -> fp16 conversions
    convert_x_kernel<<<(S_TOT * DIM + 255) / 256, 256>>>(x0, x1);
    convert_w_kernel<<<dim3(QKV_N / 32, DIM / 32), dim3(32, 8)>>>(w_qkv0, QKV_N, 0);
    convert_w_kernel<<<dim3(QKV_N / 32, DIM / 32), dim3(32, 8)>>>(w_qkv1, QKV_N, 1);
    convert_w_kernel<<<dim3(DIM / 32,   DIM / 32), dim3(32, 8)>>>(w_out0, DIM, 2);
    convert_w_kernel<<<dim3(DIM / 32,   DIM / 32), dim3(32, 8)>>>(w_out1, DIM, 3);

    // A: QKV projection (tensor cores) -> q,k fp32; v split fp16
    gemm_mma<0><<<dim3(QKV_N / 128, S_TOT / 128), 256, GEMM_SMEM>>>(nullptr);

    // B: RMSNorm + RoPE -> fp16 q hi (pre-scaled), k split
    {
        int warps = NH * S_TOT;
        norm_rope_kernel<<<(warps * 32 + 255) / 256, 256>>>(gq0, gk0, gq1, gk1);
    }

    // C: flash attention on tensor cores -> fp16 hi g_ah
    attn_mma_kernel<<<dim3(S_TOT / BQ, NH), 256, ATT_SMEM>>>();

    // D: output projection (tensor cores)
    gemm_mma<1><<<dim3(DIM / 128, S_TOT / 128), 256, GEMM_SMEM>>>(out);
}

// round 14
// speedup vs baseline: 1.5294x; 1.0032x over previous
#include <cuda_runtime.h>
#include <cuda_fp16.h>
#include <math.h>
#include <stdint.h>

#define S_TOT 2304
#define S0    2048
#define DIM   1536
#define NH    24
#define HD    64
#define QKV_N 4608
#define XK    3072          // split-fp16 K layout: [hi 0:1536 | lo 1536:3072]

// GEMM staging: CTA 128x128, K-chunk 64, tiles {Ah, Bh, Bl}, 2-stage
#define N_STAGE 24
#define KCH     64
#define PITCH   72                  // halves per smem row (pad 8)
#define TILE_B  (128 * PITCH * 2)   // 18432 B per operand tile
#define STAGE_B (3 * TILE_B)        // Ah, Bh, Bl = 55296
#define GEMM_SMEM (2 * STAGE_B)     // 110592 double-buffered

// Attention staging
#define BQ 128
#define BK 64
#define AP_B 272                    // bytes per K/V smem row (128 halves + 8 pad)
#define KV_TILE_B (64 * AP_B)       // 17408
#define STAGE2_B (2 * KV_TILE_B)    // K + V per stage = 34816
#define ATT_SMEM (2 * STAGE2_B)     // 69632 double-buffered
#define N_KT (S_TOT / BK)           // 36

// ---------------- scratch (device globals; no allocation allowed) -----------
__device__ float  g_q[NH * S_TOT * HD];       // fp32 q (pre-norm)
__device__ float  g_k[NH * S_TOT * HD];       // fp32 k (pre-norm)
__device__ __half g_qs[NH * S_TOT * 128];     // q fp16 hi (pre-scaled); lo unused
__device__ __half g_ks[NH * S_TOT * 128];     // k split fp16 [hi 64 | lo 64]
__device__ __half g_vs[NH * S_TOT * 128];     // v split fp16
__device__ __half g_xh [S_TOT * XK];          // x fp16 hi (lo plane unused)
__device__ __half g_ah [S_TOT * XK];          // attention out fp16 hi (lo unused)
__device__ __half g_wq0[QKV_N * XK];          // w_qkv0^T (split fp16), [N][K']
__device__ __half g_wq1[QKV_N * XK];
__device__ __half g_wo0[DIM * XK];            // w_out0^T
__device__ __half g_wo1[DIM * XK];

// ---------------- helpers ----------------------------------------------------
__device__ __forceinline__ uint32_t smem_u32(const void* p) {
    uint32_t a;
    asm("{ .reg .u64 t; cvta.to.shared.u64 t, %1; cvt.u32.u64 %0, t; }"
        : "=r"(a) : "l"(p));
    return a;
}
__device__ __forceinline__ void cp16(uint32_t dst, const void* src) {
    asm volatile("cp.async.cg.shared.global [%0], [%1], 16;"
                 :: "r"(dst), "l"(src));
}
__device__ __forceinline__ void ldsm_x4(uint32_t* r, uint32_t addr) {
    asm volatile("ldmatrix.sync.aligned.m8n8.x4.shared.b16 {%0,%1,%2,%3}, [%4];"
                 : "=r"(r[0]), "=r"(r[1]), "=r"(r[2]), "=r"(r[3]) : "r"(addr));
}
__device__ __forceinline__ void ldsm_x4_t(uint32_t* r, uint32_t addr) {
    asm volatile("ldmatrix.sync.aligned.m8n8.x4.trans.shared.b16 {%0,%1,%2,%3}, [%4];"
                 : "=r"(r[0]), "=r"(r[1]), "=r"(r[2]), "=r"(r[3]) : "r"(addr));
}
__device__ __forceinline__ void ldsm_x2(uint32_t* r, uint32_t addr) {
    asm volatile("ldmatrix.sync.aligned.m8n8.x2.shared.b16 {%0,%1}, [%2];"
                 : "=r"(r[0]), "=r"(r[1]) : "r"(addr));
}
__device__ __forceinline__ void mma16816(float* c, const uint32_t* a,
                                         const uint32_t* b) {
    asm volatile(
        "mma.sync.aligned.m16n8k16.row.col.f32.f16.f16.f32 "
        "{%0,%1,%2,%3}, {%4,%5,%6,%7}, {%8,%9}, {%0,%1,%2,%3};"
        : "+f"(c[0]), "+f"(c[1]), "+f"(c[2]), "+f"(c[3])
        : "r"(a[0]), "r"(a[1]), "r"(a[2]), "r"(a[3]), "r"(b[0]), "r"(b[1]));
}

// ---------------- conversion: x -> fp16 hi -----------------------------------
__global__ __launch_bounds__(256) void convert_x_kernel(
    const float* __restrict__ x0, const float* __restrict__ x1)
{
    int idx = blockIdx.x * 256 + threadIdx.x;
    if (idx >= S_TOT * DIM) return;
    int s = idx / DIM, k = idx - s * DIM;
    float v = (s < S0) ? x0[(size_t)s * DIM + k] : x1[(size_t)(s - S0) * DIM + k];
    g_xh[(size_t)s * XK + k] = __float2half_rn(v);
}

// ---------------- conversion: weights -> transposed split fp16 --------------
__global__ __launch_bounds__(256) void convert_w_kernel(
    const float* __restrict__ src, int N, int sel)
{
    __shared__ float tile[32][33];
    __half* dst = (sel == 0) ? g_wq0 : (sel == 1) ? g_wq1 : (sel == 2) ? g_wo0 : g_wo1;
    int n0 = blockIdx.x * 32;
    int k0 = blockIdx.y * 32;
    int tx = threadIdx.x, ty = threadIdx.y;   // (32, 8)
#pragma unroll
    for (int i = 0; i < 32; i += 8)
        tile[ty + i][tx] = src[(size_t)(k0 + ty + i) * N + n0 + tx];
    __syncthreads();
#pragma unroll
    for (int i = 0; i < 32; i += 8) {
        int n = n0 + ty + i;
        int k = k0 + tx;
        float v = tile[tx][ty + i];
        __half hi = __float2half_rn(v);
        __half lo = __float2half_rn(v - __half2float(hi));
        dst[(size_t)n * XK + k] = hi;
        dst[(size_t)n * XK + DIM + k] = lo;
    }
}

// ---------------- mma.sync 2-pass GEMM, 128x128 tile ------------------------
// acc = Ah*(Bh+Bl); passes separated so same-accumulator MMAs are 16 apart.
// MODE 0: A=g_xh, B=wq by modality; q,k -> fp32 g_q/g_k, v -> split-fp16 g_vs.
// MODE 1: A=g_ah, B=wo by modality; write d_out.
template <int MODE>
__global__ __launch_bounds__(256, 1) void gemm_mma(float* __restrict__ out)
{
    extern __shared__ char sm[];
    const int tid = threadIdx.x;
    const int wid = tid >> 5;
    const int lane = tid & 31;
    const int m0 = blockIdx.y * 128;
    const int n0 = blockIdx.x * 128;

    const __half* A = (MODE == 0) ? g_xh : g_ah;
    const __half* B;
    if (MODE == 0) B = (m0 < S0) ? g_wq0 : g_wq1;
    else           B = (m0 < S0) ? g_wo0 : g_wo1;

    const uint32_t smb = smem_u32(sm);

    // global->smem: 2 threads per row, 4x16B each per tile
    const int lrow  = tid >> 1;
    const int lslot = (tid & 1) * 4;
    const __half* gA = A + (size_t)(m0 + lrow) * XK + lslot * 8;
    const __half* gB = B + (size_t)(n0 + lrow) * XK + lslot * 8;
    const uint32_t sOff = (uint32_t)lrow * (PITCH * 2) + lslot * 16;

    const int wm = wid >> 2;
    const int wn = wid & 3;

    const int arow = wm * 64 + (lane & 15);
    const uint32_t aoffs = (uint32_t)arow * (PITCH * 2) + (lane >> 4) * 16;
    const int brow = wn * 32 + (lane & 7);
    const uint32_t boffs = (uint32_t)brow * (PITCH * 2) + ((lane >> 3) & 1) * 16;

    float acc[4][4][4];
#pragma unroll
    for (int i = 0; i < 4; i++)
#pragma unroll
        for (int j = 0; j < 4; j++)
#pragma unroll
            for (int e = 0; e < 4; e++) acc[i][j][e] = 0.0f;

    {
        uint32_t d = smb + sOff;
#pragma unroll
        for (int i = 0; i < 4; i++) {
            cp16(d + i * 16,              gA + i * 8);
            cp16(d + TILE_B + i * 16,     gB + i * 8);
            cp16(d + 2 * TILE_B + i * 16, gB + DIM + i * 8);
        }
        asm volatile("cp.async.commit_group;" ::: "memory");
    }

#pragma unroll 1
    for (int s = 0; s < N_STAGE; s++) {
        if (s + 1 < N_STAGE) {
            uint32_t d = smb + ((s + 1) & 1) * STAGE_B + sOff;
            const __half* pa = gA + (s + 1) * KCH;
            const __half* pb = gB + (s + 1) * KCH;
#pragma unroll
            for (int i = 0; i < 4; i++) {
                cp16(d + i * 16,              pa + i * 8);
                cp16(d + TILE_B + i * 16,     pb + i * 8);
                cp16(d + 2 * TILE_B + i * 16, pb + DIM + i * 8);
            }
            asm volatile("cp.async.commit_group;" ::: "memory");
            asm volatile("cp.async.wait_group 1;" ::: "memory");
        } else {
            asm volatile("cp.async.wait_group 0;" ::: "memory");
        }
        __syncthreads();

        const uint32_t sb = smb + (s & 1) * STAGE_B;
#pragma unroll
        for (int ks = 0; ks < 4; ks++) {
            const uint32_t aA = sb + aoffs + ks * 32;
            const uint32_t aB = sb + TILE_B + boffs + ks * 32;
            uint32_t ah[4][4], bh[4][2], bl[4][2];
#pragma unroll
            for (int mt = 0; mt < 4; mt++)
                ldsm_x4(ah[mt], aA + mt * 16 * (PITCH * 2));
#pragma unroll
            for (int nt = 0; nt < 4; nt++) {
                ldsm_x2(bh[nt], aB + nt * 8 * (PITCH * 2));
                ldsm_x2(bl[nt], aB + TILE_B + nt * 8 * (PITCH * 2));
            }
            // pass 1: all hi products (16 independent accumulators)
#pragma unroll
            for (int mt = 0; mt < 4; mt++)
#pragma unroll
                for (int nt = 0; nt < 4; nt++)
                    mma16816(acc[mt][nt], ah[mt], bh[nt]);
            // pass 2: all lo products (same acc reused 16 MMAs later)
#pragma unroll
            for (int mt = 0; mt < 4; mt++)
#pragma unroll
                for (int nt = 0; nt < 4; nt++)
                    mma16816(acc[mt][nt], ah[mt], bl[nt]);
        }
        __syncthreads();   // protect buffer (s&1) from next iteration's cp.async
    }

    // ---- epilogue ----
    const int g  = lane >> 2;
    const int tg = lane & 3;
#pragma unroll
    for (int mt = 0; mt < 4; mt++) {
        const int m = m0 + wm * 64 + mt * 16 + g;
#pragma unroll
        for (int nt = 0; nt < 4; nt++) {
            const int col = n0 + wn * 32 + nt * 8 + tg * 2;
            if (MODE == 0) {
                int tsel = col / DIM;
                int rem = col - tsel * DIM;
                int h = rem >> 6;
                int d = rem & 63;
                if (tsel < 2) {
                    float* dstb = (tsel == 0 ? g_q : g_k);
                    float* p0 = dstb + ((size_t)h * S_TOT + m) * HD + d;
                    *(float2*)p0            = make_float2(acc[mt][nt][0], acc[mt][nt][1]);
                    *(float2*)(p0 + 8 * HD) = make_float2(acc[mt][nt][2], acc[mt][nt][3]);
                } else {
                    // v -> split fp16 [hi 0:64 | lo 64:128]
                    __half* vb = g_vs + ((size_t)h * S_TOT + m) * 128 + d;
#pragma unroll
                    for (int rr = 0; rr < 2; rr++) {
                        float a0 = acc[mt][nt][rr * 2 + 0];
                        float a1 = acc[mt][nt][rr * 2 + 1];
                        __half2 hp = __floats2half2_rn(a0, a1);
                        float2 hf = __half22float2(hp);
                        __half2 lp = __floats2half2_rn(a0 - hf.x, a1 - hf.y);
                        __half* p = vb + (size_t)rr * 8 * 128;
                        *(__half2*)p        = hp;
                        *(__half2*)(p + 64) = lp;
                    }
                }
            } else {
                float* p0 = out + (size_t)m * DIM + col;
                *(float2*)p0             = make_float2(acc[mt][nt][0], acc[mt][nt][1]);
                *(float2*)(p0 + 8 * DIM) = make_float2(acc[mt][nt][2], acc[mt][nt][3]);
            }
        }
    }
}

// ---------------- RMSNorm + RoPE -> fp16 q hi (pre-scaled) / k split --------
__global__ __launch_bounds__(256) void norm_rope_kernel(
    const float* __restrict__ gq0, const float* __restrict__ gk0,
    const float* __restrict__ gq1, const float* __restrict__ gk1)
{
    const int warp = (blockIdx.x * blockDim.x + threadIdx.x) >> 5;
    const int lane = threadIdx.x & 31;
    if (warp >= NH * S_TOT) return;
    const int h = warp / S_TOT;
    const int s = warp - h * S_TOT;

    const float* gq;
    const float* gk;
    int pos;
    if (s < S0) { gq = gq0; gk = gk0; pos = s; }
    else        { gq = gq1; gk = gk1; pos = s - S0; }

    const double LN1E4_OVER_32 = 0.2878231217852968;  // ln(10000)/32
    float inv = (float)exp(-(double)lane * LN1E4_OVER_32);
    float f = (float)pos * inv;
    float cs, sn;
    sincosf(f, &sn, &cs);

    const size_t base   = ((size_t)h * S_TOT + s) * HD;
    const size_t base2  = ((size_t)h * S_TOT + s) * 128;
    const float gql = gq[lane], gqh = gq[lane + 32];
    const float gkl = gk[lane], gkh = gk[lane + 32];

    {
        float lo = g_q[base + lane];
        float hi = g_q[base + lane + 32];
        float ss = lo * lo + hi * hi;
#pragma unroll
        for (int off = 16; off; off >>= 1)
            ss += __shfl_xor_sync(0xffffffffu, ss, off);
        float r = rsqrtf(ss * (1.0f / 64.0f) + 1e-6f);
        float nl = lo * r * gql;
        float nh = hi * r * gqh;
        float q0 = (nl * cs - nh * sn) * 0.125f;   // fold 1/sqrt(D)
        float q1 = (nh * cs + nl * sn) * 0.125f;
        g_qs[base2 + lane]      = __float2half_rn(q0);
        g_qs[base2 + lane + 32] = __float2half_rn(q1);
    }
    {
        float lo = g_k[base + lane];
        float hi = g_k[base + lane + 32];
        float ss = lo * lo + hi * hi;
#pragma unroll
        for (int off = 16; off; off >>= 1)
            ss += __shfl_xor_sync(0xffffffffu, ss, off);
        float r = rsqrtf(ss * (1.0f / 64.0f) + 1e-6f);
        float nl = lo * r * gkl;
        float nh = hi * r * gkh;
        float k0 = nl * cs - nh * sn;
        float k1 = nh * cs + nl * sn;
        __half h0 = __float2half_rn(k0), h1 = __float2half_rn(k1);
        g_ks[base2 + lane]       = h0;
        g_ks[base2 + lane + 32]  = h1;
        g_ks[base2 + 64 + lane]  = __float2half_rn(k0 - __half2float(h0));
        g_ks[base2 + 96 + lane]  = __float2half_rn(k1 - __half2float(h1));
    }
}

// ---------------- flash attention on mma.sync, 2-pass split -----------------
// CTA: 128 queries x 1 head, 8 warps (16 q-rows each). K-tiles of 64 keys.
__global__ __launch_bounds__(256, 1) void attn_mma_kernel()
{
    extern __shared__ char sm[];
    const uint32_t smb = smem_u32(sm);
    const int tid = threadIdx.x;
    const int wq = tid >> 5;
    const int lane = tid & 31;
    const int h = blockIdx.y;
    const int q0 = blockIdx.x * BQ;

    const __half* Qg = g_qs + ((size_t)h * S_TOT + q0) * 128;
    const __half* Kg = g_ks + (size_t)h * S_TOT * 128;
    const __half* Vg = g_vs + (size_t)h * S_TOT * 128;

    // ---- Q tile (hi plane only) -> smem -> register fragments ----
    {
        int rid = tid >> 1;
        int hb = (tid & 1) * 64;
        const char* src = (const char*)(Qg + (size_t)rid * 128) + hb;
        uint32_t dst = smb + (uint32_t)rid * AP_B + hb;
#pragma unroll
        for (int i = 0; i < 4; i++) cp16(dst + i * 16, src + i * 16);
        asm volatile("cp.async.commit_group;" ::: "memory");
        asm volatile("cp.async.wait_group 0;" ::: "memory");
    }
    __syncthreads();

    uint32_t qh[4][4];
    {
        uint32_t base = smb + (uint32_t)(wq * 16 + (lane & 15)) * AP_B
                      + (lane >> 4) * 16;
#pragma unroll
        for (int c = 0; c < 4; c++)
            ldsm_x4(qh[c], base + c * 32);
    }
    __syncthreads();

    // cp.async coords for K/V tiles: 4 threads per 256B row
    const int rid4 = tid >> 2;
    const int slot = (tid & 3) * 64;

    // ldmatrix per-lane offsets
    const int grp = lane >> 3, lr = lane & 7;
    const uint32_t k_off = (uint32_t)((grp >> 1) * 8 + lr) * AP_B + (grp & 1) * 16;
    const uint32_t v_off = (uint32_t)((grp & 1) * 8 + lr) * AP_B + (grp >> 1) * 16;

    float o[8][4];
#pragma unroll
    for (int j = 0; j < 8; j++)
#pragma unroll
        for (int e = 0; e < 4; e++) o[j][e] = 0.0f;
    float m0 = -1e30f, m8 = -1e30f, l0 = 0.0f, l8 = 0.0f;

    // prefetch tile 0 into stage 0
    {
        const char* ks = (const char*)(Kg + (size_t)rid4 * 128) + slot;
        const char* vs = (const char*)(Vg + (size_t)rid4 * 128) + slot;
        uint32_t kd = smb + (uint32_t)rid4 * AP_B + slot;
#pragma unroll
        for (int i = 0; i < 4; i++) {
            cp16(kd + i * 16,             ks + i * 16);
            cp16(kd + KV_TILE_B + i * 16, vs + i * 16);
        }
        asm volatile("cp.async.commit_group;" ::: "memory");
    }

#pragma unroll 1
    for (int it = 0; it < N_KT; it++) {
        if (it + 1 < N_KT) {
            const size_t krow = (size_t)((it + 1) * BK + rid4) * 128;
            const char* ks = (const char*)(Kg + krow) + slot;
            const char* vs = (const char*)(Vg + krow) + slot;
            uint32_t kd = smb + ((it + 1) & 1) * STAGE2_B + (uint32_t)rid4 * AP_B + slot;
#pragma unroll
            for (int i = 0; i < 4; i++) {
                cp16(kd + i * 16,             ks + i * 16);
                cp16(kd + KV_TILE_B + i * 16, vs + i * 16);
            }
            asm volatile("cp.async.commit_group;" ::: "memory");
            asm volatile("cp.async.wait_group 1;" ::: "memory");
        } else {
            asm volatile("cp.async.wait_group 0;" ::: "memory");
        }
        __syncthreads();

        const uint32_t kb = smb + (it & 1) * STAGE2_B;
        const uint32_t vb = kb + KV_TILE_B;

        // ---- scores: S = qh * (Kh + Kl), fp32 accum (2 passes) ----
        float sc[8][4];
#pragma unroll
        for (int j = 0; j < 8; j++)
#pragma unroll
            for (int e = 0; e < 4; e++) sc[j][e] = 0.0f;

#pragma unroll
        for (int c = 0; c < 4; c++) {
            uint32_t kf[8][2], kl[8][2];
#pragma unroll
            for (int jp = 0; jp < 4; jp++) {
                uint32_t r[4];
                uint32_t a = kb + k_off + (uint32_t)jp * 16 * AP_B + c * 32;
                ldsm_x4(r, a);
                kf[2 * jp][0] = r[0]; kf[2 * jp][1] = r[1];
                kf[2 * jp + 1][0] = r[2]; kf[2 * jp + 1][1] = r[3];
                ldsm_x4(r, a + 128);
                kl[2 * jp][0] = r[0]; kl[2 * jp][1] = r[1];
                kl[2 * jp + 1][0] = r[2]; kl[2 * jp + 1][1] = r[3];
            }
            // pass 1: hi (8 independent accumulators between reuses)
#pragma unroll
            for (int j = 0; j < 8; j++)
                mma16816(sc[j], qh[c], kf[j]);
            // pass 2: lo
#pragma unroll
            for (int j = 0; j < 8; j++)
                mma16816(sc[j], qh[c], kl[j]);
        }

        // ---- online softmax on fragments ----
        float mx0 = sc[0][0], mx8 = sc[0][2];
#pragma unroll
        for (int j = 0; j < 8; j++) {
            mx0 = fmaxf(mx0, fmaxf(sc[j][0], sc[j][1]));
            mx8 = fmaxf(mx8, fmaxf(sc[j][2], sc[j][3]));
        }
        mx0 = fmaxf(mx0, __shfl_xor_sync(0xffffffffu, mx0, 1));
        mx0 = fmaxf(mx0, __shfl_xor_sync(0xffffffffu, mx0, 2));
        mx8 = fmaxf(mx8, __shfl_xor_sync(0xffffffffu, mx8, 1));
        mx8 = fmaxf(mx8, __shfl_xor_sync(0xffffffffu, mx8, 2));
        float mn0 = fmaxf(m0, mx0), mn8 = fmaxf(m8, mx8);
        float cr0 = __expf(m0 - mn0), cr8 = __expf(m8 - mn8);
        m0 = mn0; m8 = mn8;
        l0 *= cr0; l8 *= cr8;

        uint32_t pha[8], phb[8];
#pragma unroll
        for (int j = 0; j < 8; j++) {
            float p0 = __expf(sc[j][0] - m0);
            float p1 = __expf(sc[j][1] - m0);
            float p2 = __expf(sc[j][2] - m8);
            float p3 = __expf(sc[j][3] - m8);
            l0 += p0 + p1; l8 += p2 + p3;
            __half2 ha = __floats2half2_rn(p0, p1);
            __half2 hb = __floats2half2_rn(p2, p3);
            pha[j] = *(uint32_t*)&ha;
            phb[j] = *(uint32_t*)&hb;
        }
#pragma unroll
        for (int j = 0; j < 8; j++) {
            o[j][0] *= cr0; o[j][1] *= cr0;
            o[j][2] *= cr8; o[j][3] *= cr8;
        }

        // ---- O += Ph * (Vh + Vl) (2 passes) ----
#pragma unroll
        for (int c = 0; c < 4; c++) {
            uint32_t a_h[4] = {pha[2 * c], phb[2 * c], pha[2 * c + 1], phb[2 * c + 1]};
            uint32_t vh[8][2], vl[8][2];
#pragma unroll
            for (int jp = 0; jp < 4; jp++) {
                uint32_t r[4];
                uint32_t a = vb + v_off + (uint32_t)c * 16 * AP_B + jp * 32;
                ldsm_x4_t(r, a);
                vh[2 * jp][0] = r[0]; vh[2 * jp][1] = r[1];
                vh[2 * jp + 1][0] = r[2]; vh[2 * jp + 1][1] = r[3];
                ldsm_x4_t(r, a + 128);
                vl[2 * jp][0] = r[0]; vl[2 * jp][1] = r[1];
                vl[2 * jp + 1][0] = r[2]; vl[2 * jp + 1][1] = r[3];
            }
            // pass 1: hi
#pragma unroll
            for (int j = 0; j < 8; j++)
                mma16816(o[j], a_h, vh[j]);
            // pass 2: lo
#pragma unroll
            for (int j = 0; j < 8; j++)
                mma16816(o[j], a_h, vl[j]);
        }
        __syncthreads();
    }

    // ---- finalize: divide by l, write fp16 hi into g_ah ----
    l0 += __shfl_xor_sync(0xffffffffu, l0, 1);
    l0 += __shfl_xor_sync(0xffffffffu, l0, 2);
    l8 += __shfl_xor_sync(0xffffffffu, l8, 1);
    l8 += __shfl_xor_sync(0xffffffffu, l8, 2);
    const float iv0 = 1.0f / l0, iv8 = 1.0f / l8;

    const int g = lane >> 2, tg = lane & 3;
    const int r0 = q0 + wq * 16 + g;
    __half* out0 = g_ah + (size_t)r0 * XK + h * HD + tg * 2;
    __half* out8 = out0 + (size_t)8 * XK;
#pragma unroll
    for (int j = 0; j < 8; j++) {
        *(__half2*)(out0 + 8 * j) = __floats2half2_rn(o[j][0] * iv0, o[j][1] * iv0);
        *(__half2*)(out8 + 8 * j) = __floats2half2_rn(o[j][2] * iv8, o[j][3] * iv8);
    }
}

// ---------------- launch ----------------------------------------------------
extern "C" void kernel_launch(void* const* d_in, const int* in_sizes, int n_in,
                              void* d_out, int out_size)
{
    const float* x0     = (const float*)d_in[0];
    const float* x1     = (const float*)d_in[1];
    const float* w_qkv0 = (const float*)d_in[2];
    const float* w_qkv1 = (const float*)d_in[3];
    const float* w_out0 = (const float*)d_in[4];
    const float* w_out1 = (const float*)d_in[5];
    const float* gq0    = (const float*)d_in[6];
    const float* gk0    = (const float*)d_in[7];
    const float* gq1    = (const float*)d_in[8];
    const float* gk1    = (const float*)d_in[9];
    float* out = (float*)d_out;

    cudaFuncSetAttribute(gemm_mma<0>, cudaFuncAttributeMaxDynamicSharedMemorySize, GEMM_SMEM);
    cudaFuncSetAttribute(gemm_mma<1>, cudaFuncAttributeMaxDynamicSharedMemorySize, GEMM_SMEM);
    cudaFuncSetAttribute(attn_mma_kernel, cudaFuncAttributeMaxDynamicSharedMemorySize, ATT_SMEM);

    // 0: fp32 -> fp16 conversions
    convert_x_kernel<<<(S_TOT * DIM + 255) / 256, 256>>>(x0, x1);
    convert_w_kernel<<<dim3(QKV_N / 32, DIM / 32), dim3(32, 8)>>>(w_qkv0, QKV_N, 0);
    convert_w_kernel<<<dim3(QKV_N / 32, DIM / 32), dim3(32, 8)>>>(w_qkv1, QKV_N, 1);
    convert_w_kernel<<<dim3(DIM / 32,   DIM / 32), dim3(32, 8)>>>(w_out0, DIM, 2);
    convert_w_kernel<<<dim3(DIM / 32,   DIM / 32), dim3(32, 8)>>>(w_out1, DIM, 3);

    // A: QKV projection (tensor cores) -> q,k fp32; v split fp16
    gemm_mma<0><<<dim3(QKV_N / 128, S_TOT / 128), 256, GEMM_SMEM>>>(nullptr);

    // B: RMSNorm + RoPE -> fp16 q hi (pre-scaled), k split
    {
        int warps = NH * S_TOT;
        norm_rope_kernel<<<(warps * 32 + 255) / 256, 256>>>(gq0, gk0, gq1, gk1);
    }

    // C: flash attention on tensor cores -> fp16 hi g_ah
    attn_mma_kernel<<<dim3(S_TOT / BQ, NH), 256, ATT_SMEM>>>();

    // D: output projection (tensor cores)
    gemm_mma<1><<<dim3(DIM / 128, S_TOT / 128), 256, GEMM_SMEM>>>(out);
}